// round 1
// baseline (speedup 1.0000x reference)
#include <cuda_runtime.h>
#include <math.h>

#define B_    2
#define T_    2048
#define NTOK  4096
#define DIM_  1024
#define HID_  4096
#define NH_   16
#define HD_   64

// Scratch (allocation-free rule: __device__ globals)
__device__ float g_h1 [NTOK * DIM_];
__device__ float g_qkv[NTOK * 3 * DIM_];
__device__ float g_att[NTOK * DIM_];
__device__ float g_x2 [NTOK * DIM_];
__device__ float g_h2 [NTOK * DIM_];
__device__ float g_f1 [NTOK * HID_];

// ---------------------------------------------------------------------------
// LayerNorm: one block per row, 256 threads
// ---------------------------------------------------------------------------
__global__ __launch_bounds__(256) void ln_kernel(
    const float* __restrict__ x, const float* __restrict__ w,
    const float* __restrict__ b, float* __restrict__ y)
{
    int row = blockIdx.x;
    const float* xr = x + (size_t)row * DIM_;
    float s = 0.f, s2 = 0.f;
    for (int i = threadIdx.x; i < DIM_; i += 256) {
        float v = xr[i]; s += v; s2 += v * v;
    }
    __shared__ float rs[8], rs2[8];
    for (int o = 16; o; o >>= 1) {
        s  += __shfl_down_sync(0xffffffffu, s,  o);
        s2 += __shfl_down_sync(0xffffffffu, s2, o);
    }
    int wid = threadIdx.x >> 5, lane = threadIdx.x & 31;
    if (!lane) { rs[wid] = s; rs2[wid] = s2; }
    __syncthreads();
    __shared__ float mu_s, inv_s;
    if (threadIdx.x == 0) {
        float t = 0.f, t2 = 0.f;
        for (int i = 0; i < 8; i++) { t += rs[i]; t2 += rs2[i]; }
        float mu = t / (float)DIM_;
        float var = t2 / (float)DIM_ - mu * mu;
        mu_s = mu;
        inv_s = rsqrtf(var + 1e-5f);
    }
    __syncthreads();
    float mu = mu_s, inv = inv_s;
    float* yr = y + (size_t)row * DIM_;
    for (int i = threadIdx.x; i < DIM_; i += 256)
        yr[i] = (xr[i] - mu) * inv * w[i] + b[i];
}

// ---------------------------------------------------------------------------
// SGEMM C[M,N] = A[M,K] * B[K,N], 64x64 tile, BK=16, 256 thr, 4x4/thread
// EPI: 0 = none, 1 = +bias +residual, 2 = +bias, exact GELU
// ---------------------------------------------------------------------------
template <int EPI>
__global__ __launch_bounds__(256) void gemm64(
    const float* __restrict__ A, const float* __restrict__ Bm,
    const float* __restrict__ bias, const float* __restrict__ res,
    float* __restrict__ C, int M, int N, int K)
{
    __shared__ float As[64][16];
    __shared__ float Bs[16][64];
    int tid = threadIdx.x;
    int tx = tid & 15, ty = tid >> 4;
    int row0 = blockIdx.y * 64, col0 = blockIdx.x * 64;
    int ar = tid >> 2,  ac = (tid & 3)  * 4;
    int br = tid >> 4,  bc = (tid & 15) * 4;

    float acc[4][4] = {};
    const float* Ap = A  + (size_t)(row0 + ar) * K + ac;
    const float* Bp = Bm + (size_t)br * N + col0 + bc;

    for (int kt = 0; kt < K; kt += 16) {
        float4 av = *(const float4*)(Ap + kt);
        float4 bv = *(const float4*)(Bp + (size_t)kt * N);
        *(float4*)&As[ar][ac] = av;
        *(float4*)&Bs[br][bc] = bv;
        __syncthreads();
#pragma unroll
        for (int k = 0; k < 16; k++) {
            float4 b4 = *(const float4*)&Bs[k][tx * 4];
#pragma unroll
            for (int i = 0; i < 4; i++) {
                float a = As[ty * 4 + i][k];
                acc[i][0] += a * b4.x;
                acc[i][1] += a * b4.y;
                acc[i][2] += a * b4.z;
                acc[i][3] += a * b4.w;
            }
        }
        __syncthreads();
    }

#pragma unroll
    for (int i = 0; i < 4; i++) {
        int r = row0 + ty * 4 + i;
#pragma unroll
        for (int j = 0; j < 4; j++) {
            int c = col0 + tx * 4 + j;
            float v = acc[i][j];
            if (EPI == 1) v += bias[c] + res[(size_t)r * N + c];
            if (EPI == 2) {
                v += bias[c];
                v = 0.5f * v * (1.f + erff(v * 0.70710678118654752f));
            }
            C[(size_t)r * N + c] = v;
        }
    }
}

// ---------------------------------------------------------------------------
// Flash-style causal attention with key padding mask.
// Grid: (T/64 q-tiles, heads, batch). 256 threads, 4x4/thread over 64x64.
// qkv layout per token row (3*DIM): q @ h*64, k @ DIM+h*64, v @ 2*DIM+h*64
// ---------------------------------------------------------------------------
__global__ __launch_bounds__(256) void attn_kernel(
    const float* __restrict__ qkv, const int* __restrict__ kpm,
    float* __restrict__ out)
{
    extern __shared__ float sm[];
    float* Qs   = sm;               // [64][64]
    float* Ks   = Qs + 64 * 64;     // [64][65] padded
    float* Vs   = Ks + 64 * 65;     // [64][64]
    float* Ss   = Vs + 64 * 64;     // [64][65] padded
    float* mrow = Ss + 64 * 65;     // [64]
    float* lrow = mrow + 64;        // [64]
    float* arow = lrow + 64;        // [64]
    float* padv = arow + 64;        // [64]
    float* pred = padv + 64;        // [64][4]

    int qb = blockIdx.x, h = blockIdx.y, b = blockIdx.z;
    int tid = threadIdx.x;
    int tx = tid & 15, ty = tid >> 4;
    const float scale = 0.125f;     // 1/sqrt(64)
    const int lds = 3 * DIM_;

    // Load Q tile (pre-scaled)
    size_t qbase = ((size_t)(b * T_ + qb * 64)) * lds + h * HD_;
    for (int idx = tid; idx < 64 * 16; idx += 256) {
        int r = idx >> 4, c4 = (idx & 15) * 4;
        float4 v = *(const float4*)(qkv + qbase + (size_t)r * lds + c4);
        v.x *= scale; v.y *= scale; v.z *= scale; v.w *= scale;
        *(float4*)&Qs[r * 64 + c4] = v;
    }
    if (tid < 64) { mrow[tid] = -1e30f; lrow[tid] = 0.f; }

    float o[4][4] = {};

    for (int kt = 0; kt <= qb; kt++) {
        __syncthreads();   // protect prior-iter Ss/Vs reads & init
        size_t kbase = ((size_t)(b * T_ + kt * 64)) * lds + DIM_ + h * HD_;
        size_t vbase = kbase + DIM_;
        for (int idx = tid; idx < 64 * 64; idx += 256) {
            int r = idx >> 6, c = idx & 63;
            Ks[r * 65 + c] = qkv[kbase + (size_t)r * lds + c];
        }
        for (int idx = tid; idx < 64 * 16; idx += 256) {
            int r = idx >> 4, c4 = (idx & 15) * 4;
            *(float4*)&Vs[r * 64 + c4] =
                *(const float4*)(qkv + vbase + (size_t)r * lds + c4);
        }
        if (tid < 64)
            padv[tid] = kpm[b * T_ + kt * 64 + tid] ? -1e9f : 0.f;
        __syncthreads();

        // S = (Q*scale) K^T
        float s[4][4] = {};
#pragma unroll 16
        for (int d = 0; d < 64; d++) {
            float k0 = Ks[(tx * 4 + 0) * 65 + d];
            float k1 = Ks[(tx * 4 + 1) * 65 + d];
            float k2 = Ks[(tx * 4 + 2) * 65 + d];
            float k3 = Ks[(tx * 4 + 3) * 65 + d];
#pragma unroll
            for (int i = 0; i < 4; i++) {
                float q = Qs[(ty * 4 + i) * 64 + d];
                s[i][0] += q * k0; s[i][1] += q * k1;
                s[i][2] += q * k2; s[i][3] += q * k3;
            }
        }
        bool diag = (kt == qb);
#pragma unroll
        for (int i = 0; i < 4; i++) {
            int r = ty * 4 + i;
#pragma unroll
            for (int j = 0; j < 4; j++) {
                int c = tx * 4 + j;
                float v = s[i][j] + padv[c];
                if (diag && c > r) v = -1e30f;
                Ss[r * 65 + c] = v;
            }
        }
        __syncthreads();

        // row max (4 partials/row)
        {
            int r = tid >> 2, part = tid & 3, c0 = part * 16;
            float pm = -1e30f;
            for (int c = c0; c < c0 + 16; c++)
                pm = fmaxf(pm, Ss[r * 65 + c]);
            pred[r * 4 + part] = pm;
        }
        __syncthreads();
        if (tid < 64) {
            int r = tid;
            float mn = fmaxf(fmaxf(pred[r*4], pred[r*4+1]),
                             fmaxf(pred[r*4+2], pred[r*4+3]));
            mn = fmaxf(mn, mrow[r]);
            arow[r] = __expf(mrow[r] - mn);
            mrow[r] = mn;
        }
        __syncthreads();
        // exp + row sum
        {
            int r = tid >> 2, part = tid & 3, c0 = part * 16;
            float mn = mrow[r], ps = 0.f;
            for (int c = c0; c < c0 + 16; c++) {
                float p = __expf(Ss[r * 65 + c] - mn);
                Ss[r * 65 + c] = p;
                ps += p;
            }
            pred[r * 4 + part] = ps;
        }
        __syncthreads();
        if (tid < 64) {
            int r = tid;
            lrow[r] = lrow[r] * arow[r] +
                      pred[r*4] + pred[r*4+1] + pred[r*4+2] + pred[r*4+3];
        }
        __syncthreads();

        // O = O*alpha + P V
        float al[4];
#pragma unroll
        for (int i = 0; i < 4; i++) al[i] = arow[ty * 4 + i];
#pragma unroll
        for (int i = 0; i < 4; i++) {
            o[i][0] *= al[i]; o[i][1] *= al[i];
            o[i][2] *= al[i]; o[i][3] *= al[i];
        }
#pragma unroll 8
        for (int c = 0; c < 64; c++) {
            float4 v = *(const float4*)&Vs[c * 64 + tx * 4];
#pragma unroll
            for (int i = 0; i < 4; i++) {
                float p = Ss[(ty * 4 + i) * 65 + c];
                o[i][0] += p * v.x; o[i][1] += p * v.y;
                o[i][2] += p * v.z; o[i][3] += p * v.w;
            }
        }
    }

    // write O / l
#pragma unroll
    for (int i = 0; i < 4; i++) {
        int r = ty * 4 + i;
        float invl = 1.f / lrow[r];
        size_t ob = ((size_t)(b * T_ + qb * 64 + r)) * DIM_ + h * HD_ + tx * 4;
        out[ob + 0] = o[i][0] * invl;
        out[ob + 1] = o[i][1] * invl;
        out[ob + 2] = o[i][2] * invl;
        out[ob + 3] = o[i][3] * invl;
    }
}

// ---------------------------------------------------------------------------
extern "C" void kernel_launch(void* const* d_in, const int* in_sizes, int n_in,
                              void* d_out, int out_size)
{
    const float* x     = (const float*)d_in[0];
    const int*   kpm   = (const int*)  d_in[1];
    const float* ln1w  = (const float*)d_in[2];
    const float* ln1b  = (const float*)d_in[3];
    const float* qkvw  = (const float*)d_in[4];
    const float* projw = (const float*)d_in[5];
    const float* projb = (const float*)d_in[6];
    const float* ln2w  = (const float*)d_in[7];
    const float* ln2b  = (const float*)d_in[8];
    const float* fc1w  = (const float*)d_in[9];
    const float* fc1b  = (const float*)d_in[10];
    const float* fc2w  = (const float*)d_in[11];
    const float* fc2b  = (const float*)d_in[12];
    float* out = (float*)d_out;

    float *h1, *qkv, *att, *x2, *h2, *f1;
    cudaGetSymbolAddress((void**)&h1,  g_h1);
    cudaGetSymbolAddress((void**)&qkv, g_qkv);
    cudaGetSymbolAddress((void**)&att, g_att);
    cudaGetSymbolAddress((void**)&x2,  g_x2);
    cudaGetSymbolAddress((void**)&h2,  g_h2);
    cudaGetSymbolAddress((void**)&f1,  g_f1);

    const int smem = 68096;  // attention dynamic smem bytes
    cudaFuncSetAttribute(attn_kernel,
                         cudaFuncAttributeMaxDynamicSharedMemorySize, smem);

    // 1) LN1
    ln_kernel<<<NTOK, 256>>>(x, ln1w, ln1b, h1);
    // 2) QKV GEMM [4096,1024]x[1024,3072]
    gemm64<0><<<dim3(3 * DIM_ / 64, NTOK / 64), 256>>>(
        h1, qkvw, nullptr, nullptr, qkv, NTOK, 3 * DIM_, DIM_);
    // 3) Attention
    attn_kernel<<<dim3(T_ / 64, NH_, B_), 256, smem>>>(qkv, kpm, att);
    // 4) proj GEMM + bias + residual(x)
    gemm64<1><<<dim3(DIM_ / 64, NTOK / 64), 256>>>(
        att, projw, projb, x, x2, NTOK, DIM_, DIM_);
    // 5) LN2
    ln_kernel<<<NTOK, 256>>>(x2, ln2w, ln2b, h2);
    // 6) fc1 GEMM + bias + exact GELU
    gemm64<2><<<dim3(HID_ / 64, NTOK / 64), 256>>>(
        h2, fc1w, fc1b, nullptr, f1, NTOK, HID_, DIM_);
    // 7) fc2 GEMM + bias + residual(x2) -> out
    gemm64<1><<<dim3(DIM_ / 64, NTOK / 64), 256>>>(
        f1, fc2w, fc2b, x2, out, NTOK, DIM_, HID_);
}

// round 2
// speedup vs baseline: 2.2077x; 2.2077x over previous
#include <cuda_runtime.h>
#include <math.h>

#define B_    2
#define T_    2048
#define NTOK  4096
#define DIM_  1024
#define HID_  4096
#define NH_   16
#define HD_   64

// Scratch (allocation-free rule: __device__ globals)
__device__ float g_h1 [NTOK * DIM_];
__device__ float g_qkv[NTOK * 3 * DIM_];
__device__ float g_att[NTOK * DIM_];
__device__ float g_x2 [NTOK * DIM_];
__device__ float g_h2 [NTOK * DIM_];
__device__ float g_f1 [NTOK * HID_];

// ---------------------------------------------------------------------------
// LayerNorm: one block per row, 256 threads
// ---------------------------------------------------------------------------
__global__ __launch_bounds__(256) void ln_kernel(
    const float* __restrict__ x, const float* __restrict__ w,
    const float* __restrict__ b, float* __restrict__ y)
{
    int row = blockIdx.x;
    const float* xr = x + (size_t)row * DIM_;
    float s = 0.f, s2 = 0.f;
    for (int i = threadIdx.x; i < DIM_; i += 256) {
        float v = xr[i]; s += v; s2 += v * v;
    }
    __shared__ float rs[8], rs2[8];
    for (int o = 16; o; o >>= 1) {
        s  += __shfl_down_sync(0xffffffffu, s,  o);
        s2 += __shfl_down_sync(0xffffffffu, s2, o);
    }
    int wid = threadIdx.x >> 5, lane = threadIdx.x & 31;
    if (!lane) { rs[wid] = s; rs2[wid] = s2; }
    __syncthreads();
    __shared__ float mu_s, inv_s;
    if (threadIdx.x == 0) {
        float t = 0.f, t2 = 0.f;
        for (int i = 0; i < 8; i++) { t += rs[i]; t2 += rs2[i]; }
        float mu = t / (float)DIM_;
        float var = t2 / (float)DIM_ - mu * mu;
        mu_s = mu;
        inv_s = rsqrtf(var + 1e-5f);
    }
    __syncthreads();
    float mu = mu_s, inv = inv_s;
    float* yr = y + (size_t)row * DIM_;
    for (int i = threadIdx.x; i < DIM_; i += 256)
        yr[i] = (xr[i] - mu) * inv * w[i] + b[i];
}

// ---------------------------------------------------------------------------
// TF32 tensor-core GEMM: C[M,N] = A[M,K] * B[K,N]  (both row-major fp32)
// 128x128 CTA tile, BK=32, 256 threads = 8 warps (2x4), warp tile 64x32.
// mma.sync.aligned.m16n8k8.row.col.f32.tf32.tf32.f32
// EPI: 0 = none, 1 = +bias +residual, 2 = +bias + exact GELU
// ---------------------------------------------------------------------------
__device__ __forceinline__ unsigned f2tf32(float f) {
    unsigned u;
    asm("cvt.rna.tf32.f32 %0, %1;" : "=r"(u) : "f"(f));
    return u;
}

__device__ __forceinline__ void mma_tf32(float* c, const unsigned* a,
                                         const unsigned* b) {
    asm volatile(
        "mma.sync.aligned.m16n8k8.row.col.f32.tf32.tf32.f32 "
        "{%0,%1,%2,%3}, {%4,%5,%6,%7}, {%8,%9}, {%0,%1,%2,%3};"
        : "+f"(c[0]), "+f"(c[1]), "+f"(c[2]), "+f"(c[3])
        : "r"(a[0]), "r"(a[1]), "r"(a[2]), "r"(a[3]),
          "r"(b[0]), "r"(b[1]));
}

template <int EPI>
__global__ __launch_bounds__(256) void gemm_tf32(
    const float* __restrict__ A, const float* __restrict__ Bm,
    const float* __restrict__ bias, const float* __restrict__ res,
    float* __restrict__ C, int M, int N, int K)
{
    __shared__ unsigned As[128][36];   // pad 4 -> A-frag loads conflict-free
    __shared__ unsigned Bs[32][136];   // pad 8 -> B-frag loads conflict-free

    int tid  = threadIdx.x;
    int lane = tid & 31, warp = tid >> 5;
    int wr = warp >> 2, wc = warp & 3;            // 2x4 warp grid
    int row0 = blockIdx.y * 128, col0 = blockIdx.x * 128;

    int arow = tid >> 3, acol = (tid & 7) * 4;    // A gmem tile: 32r x 32c /pass
    int brow = tid >> 5, bcol = (tid & 31) * 4;   // B gmem tile: 8r x 128c /pass

    int g = lane >> 2, t = lane & 3;              // groupID, threadID-in-group

    float acc[4][4][4];
#pragma unroll
    for (int mt = 0; mt < 4; mt++)
#pragma unroll
        for (int nt = 0; nt < 4; nt++)
#pragma unroll
            for (int i = 0; i < 4; i++) acc[mt][nt][i] = 0.f;

    for (int kt = 0; kt < K; kt += 32) {
        // ---- global -> smem (with tf32 rounding) ----
#pragma unroll
        for (int i = 0; i < 4; i++) {
            int r = i * 32 + arow;
            float4 v = *(const float4*)(A + (size_t)(row0 + r) * K + kt + acol);
            As[r][acol + 0] = f2tf32(v.x);
            As[r][acol + 1] = f2tf32(v.y);
            As[r][acol + 2] = f2tf32(v.z);
            As[r][acol + 3] = f2tf32(v.w);
        }
#pragma unroll
        for (int i = 0; i < 4; i++) {
            int r = i * 8 + brow;
            float4 v = *(const float4*)(Bm + (size_t)(kt + r) * N + col0 + bcol);
            Bs[r][bcol + 0] = f2tf32(v.x);
            Bs[r][bcol + 1] = f2tf32(v.y);
            Bs[r][bcol + 2] = f2tf32(v.z);
            Bs[r][bcol + 3] = f2tf32(v.w);
        }
        __syncthreads();

        // ---- 4 k-steps of m16n8k8 ----
#pragma unroll
        for (int ks = 0; ks < 4; ks++) {
            int k0 = ks * 8;
            unsigned af[4][4], bf[4][2];
#pragma unroll
            for (int mt = 0; mt < 4; mt++) {
                int r = wr * 64 + mt * 16 + g;
                af[mt][0] = As[r    ][k0 + t];
                af[mt][1] = As[r + 8][k0 + t];
                af[mt][2] = As[r    ][k0 + t + 4];
                af[mt][3] = As[r + 8][k0 + t + 4];
            }
#pragma unroll
            for (int nt = 0; nt < 4; nt++) {
                int n = wc * 32 + nt * 8 + g;
                bf[nt][0] = Bs[k0 + t    ][n];
                bf[nt][1] = Bs[k0 + t + 4][n];
            }
#pragma unroll
            for (int mt = 0; mt < 4; mt++)
#pragma unroll
                for (int nt = 0; nt < 4; nt++)
                    mma_tf32(acc[mt][nt], af[mt], bf[nt]);
        }
        __syncthreads();
    }

    // ---- epilogue: c0,c1 at (r, c..c+1); c2,c3 at (r+8, c..c+1) ----
#pragma unroll
    for (int mt = 0; mt < 4; mt++) {
#pragma unroll
        for (int nt = 0; nt < 4; nt++) {
            int r = row0 + wr * 64 + mt * 16 + g;
            int c = col0 + wc * 32 + nt * 8 + t * 2;
#pragma unroll
            for (int half = 0; half < 2; half++) {
                int rr = r + half * 8;
                float v0 = acc[mt][nt][half * 2 + 0];
                float v1 = acc[mt][nt][half * 2 + 1];
                if (EPI == 1) {
                    const float* rp = res + (size_t)rr * N + c;
                    v0 += bias[c]     + rp[0];
                    v1 += bias[c + 1] + rp[1];
                } else if (EPI == 2) {
                    v0 += bias[c];
                    v1 += bias[c + 1];
                    v0 = 0.5f * v0 * (1.f + erff(v0 * 0.70710678118654752f));
                    v1 = 0.5f * v1 * (1.f + erff(v1 * 0.70710678118654752f));
                }
                float2 o = make_float2(v0, v1);
                *(float2*)(C + (size_t)rr * N + c) = o;
            }
        }
    }
}

// ---------------------------------------------------------------------------
// Flash-style causal attention with key padding mask (fp32, unchanged).
// ---------------------------------------------------------------------------
__global__ __launch_bounds__(256) void attn_kernel(
    const float* __restrict__ qkv, const int* __restrict__ kpm,
    float* __restrict__ out)
{
    extern __shared__ float sm[];
    float* Qs   = sm;               // [64][64]
    float* Ks   = Qs + 64 * 64;     // [64][65] padded
    float* Vs   = Ks + 64 * 65;     // [64][64]
    float* Ss   = Vs + 64 * 64;     // [64][65] padded
    float* mrow = Ss + 64 * 65;     // [64]
    float* lrow = mrow + 64;        // [64]
    float* arow = lrow + 64;        // [64]
    float* padv = arow + 64;        // [64]
    float* pred = padv + 64;        // [64][4]

    int qb = blockIdx.x, h = blockIdx.y, b = blockIdx.z;
    int tid = threadIdx.x;
    int tx = tid & 15, ty = tid >> 4;
    const float scale = 0.125f;     // 1/sqrt(64)
    const int lds = 3 * DIM_;

    size_t qbase = ((size_t)(b * T_ + qb * 64)) * lds + h * HD_;
    for (int idx = tid; idx < 64 * 16; idx += 256) {
        int r = idx >> 4, c4 = (idx & 15) * 4;
        float4 v = *(const float4*)(qkv + qbase + (size_t)r * lds + c4);
        v.x *= scale; v.y *= scale; v.z *= scale; v.w *= scale;
        *(float4*)&Qs[r * 64 + c4] = v;
    }
    if (tid < 64) { mrow[tid] = -1e30f; lrow[tid] = 0.f; }

    float o[4][4] = {};

    for (int kt = 0; kt <= qb; kt++) {
        __syncthreads();
        size_t kbase = ((size_t)(b * T_ + kt * 64)) * lds + DIM_ + h * HD_;
        size_t vbase = kbase + DIM_;
        for (int idx = tid; idx < 64 * 64; idx += 256) {
            int r = idx >> 6, c = idx & 63;
            Ks[r * 65 + c] = qkv[kbase + (size_t)r * lds + c];
        }
        for (int idx = tid; idx < 64 * 16; idx += 256) {
            int r = idx >> 4, c4 = (idx & 15) * 4;
            *(float4*)&Vs[r * 64 + c4] =
                *(const float4*)(qkv + vbase + (size_t)r * lds + c4);
        }
        if (tid < 64)
            padv[tid] = kpm[b * T_ + kt * 64 + tid] ? -1e9f : 0.f;
        __syncthreads();

        float s[4][4] = {};
#pragma unroll 16
        for (int d = 0; d < 64; d++) {
            float k0 = Ks[(tx * 4 + 0) * 65 + d];
            float k1 = Ks[(tx * 4 + 1) * 65 + d];
            float k2 = Ks[(tx * 4 + 2) * 65 + d];
            float k3 = Ks[(tx * 4 + 3) * 65 + d];
#pragma unroll
            for (int i = 0; i < 4; i++) {
                float q = Qs[(ty * 4 + i) * 64 + d];
                s[i][0] += q * k0; s[i][1] += q * k1;
                s[i][2] += q * k2; s[i][3] += q * k3;
            }
        }
        bool diag = (kt == qb);
#pragma unroll
        for (int i = 0; i < 4; i++) {
            int r = ty * 4 + i;
#pragma unroll
            for (int j = 0; j < 4; j++) {
                int c = tx * 4 + j;
                float v = s[i][j] + padv[c];
                if (diag && c > r) v = -1e30f;
                Ss[r * 65 + c] = v;
            }
        }
        __syncthreads();

        {
            int r = tid >> 2, part = tid & 3, c0 = part * 16;
            float pm = -1e30f;
            for (int c = c0; c < c0 + 16; c++)
                pm = fmaxf(pm, Ss[r * 65 + c]);
            pred[r * 4 + part] = pm;
        }
        __syncthreads();
        if (tid < 64) {
            int r = tid;
            float mn = fmaxf(fmaxf(pred[r*4], pred[r*4+1]),
                             fmaxf(pred[r*4+2], pred[r*4+3]));
            mn = fmaxf(mn, mrow[r]);
            arow[r] = __expf(mrow[r] - mn);
            mrow[r] = mn;
        }
        __syncthreads();
        {
            int r = tid >> 2, part = tid & 3, c0 = part * 16;
            float mn = mrow[r], ps = 0.f;
            for (int c = c0; c < c0 + 16; c++) {
                float p = __expf(Ss[r * 65 + c] - mn);
                Ss[r * 65 + c] = p;
                ps += p;
            }
            pred[r * 4 + part] = ps;
        }
        __syncthreads();
        if (tid < 64) {
            int r = tid;
            lrow[r] = lrow[r] * arow[r] +
                      pred[r*4] + pred[r*4+1] + pred[r*4+2] + pred[r*4+3];
        }
        __syncthreads();

        float al[4];
#pragma unroll
        for (int i = 0; i < 4; i++) al[i] = arow[ty * 4 + i];
#pragma unroll
        for (int i = 0; i < 4; i++) {
            o[i][0] *= al[i]; o[i][1] *= al[i];
            o[i][2] *= al[i]; o[i][3] *= al[i];
        }
#pragma unroll 8
        for (int c = 0; c < 64; c++) {
            float4 v = *(const float4*)&Vs[c * 64 + tx * 4];
#pragma unroll
            for (int i = 0; i < 4; i++) {
                float p = Ss[(ty * 4 + i) * 65 + c];
                o[i][0] += p * v.x; o[i][1] += p * v.y;
                o[i][2] += p * v.z; o[i][3] += p * v.w;
            }
        }
    }

#pragma unroll
    for (int i = 0; i < 4; i++) {
        int r = ty * 4 + i;
        float invl = 1.f / lrow[r];
        size_t ob = ((size_t)(b * T_ + qb * 64 + r)) * DIM_ + h * HD_ + tx * 4;
        out[ob + 0] = o[i][0] * invl;
        out[ob + 1] = o[i][1] * invl;
        out[ob + 2] = o[i][2] * invl;
        out[ob + 3] = o[i][3] * invl;
    }
}

// ---------------------------------------------------------------------------
extern "C" void kernel_launch(void* const* d_in, const int* in_sizes, int n_in,
                              void* d_out, int out_size)
{
    const float* x     = (const float*)d_in[0];
    const int*   kpm   = (const int*)  d_in[1];
    const float* ln1w  = (const float*)d_in[2];
    const float* ln1b  = (const float*)d_in[3];
    const float* qkvw  = (const float*)d_in[4];
    const float* projw = (const float*)d_in[5];
    const float* projb = (const float*)d_in[6];
    const float* ln2w  = (const float*)d_in[7];
    const float* ln2b  = (const float*)d_in[8];
    const float* fc1w  = (const float*)d_in[9];
    const float* fc1b  = (const float*)d_in[10];
    const float* fc2w  = (const float*)d_in[11];
    const float* fc2b  = (const float*)d_in[12];
    float* out = (float*)d_out;

    float *h1, *qkv, *att, *x2, *h2, *f1;
    cudaGetSymbolAddress((void**)&h1,  g_h1);
    cudaGetSymbolAddress((void**)&qkv, g_qkv);
    cudaGetSymbolAddress((void**)&att, g_att);
    cudaGetSymbolAddress((void**)&x2,  g_x2);
    cudaGetSymbolAddress((void**)&h2,  g_h2);
    cudaGetSymbolAddress((void**)&f1,  g_f1);

    const int smem = 68096;  // attention dynamic smem bytes
    cudaFuncSetAttribute(attn_kernel,
                         cudaFuncAttributeMaxDynamicSharedMemorySize, smem);

    // 1) LN1
    ln_kernel<<<NTOK, 256>>>(x, ln1w, ln1b, h1);
    // 2) QKV GEMM [4096,1024]x[1024,3072]
    gemm_tf32<0><<<dim3(3 * DIM_ / 128, NTOK / 128), 256>>>(
        h1, qkvw, nullptr, nullptr, qkv, NTOK, 3 * DIM_, DIM_);
    // 3) Attention
    attn_kernel<<<dim3(T_ / 64, NH_, B_), 256, smem>>>(qkv, kpm, att);
    // 4) proj GEMM + bias + residual(x)
    gemm_tf32<1><<<dim3(DIM_ / 128, NTOK / 128), 256>>>(
        att, projw, projb, x, x2, NTOK, DIM_, DIM_);
    // 5) LN2
    ln_kernel<<<NTOK, 256>>>(x2, ln2w, ln2b, h2);
    // 6) fc1 GEMM + bias + exact GELU
    gemm_tf32<2><<<dim3(HID_ / 128, NTOK / 128), 256>>>(
        h2, fc1w, fc1b, nullptr, f1, NTOK, HID_, DIM_);
    // 7) fc2 GEMM + bias + residual(x2) -> out
    gemm_tf32<1><<<dim3(DIM_ / 128, NTOK / 128), 256>>>(
        f1, fc2w, fc2b, x2, out, NTOK, DIM_, HID_);
}